// round 14
// baseline (speedup 1.0000x reference)
#include <cuda_runtime.h>
#include <cuda_fp16.h>
#include <cstdint>

#define Bsz 512
#define Tt  256
#define Hh  256
#define Pp  14
#define GSIZE 16
#define STRD 264   // staging row stride in halves (528B: ldmatrix conflict-free)

// ---------------- global scratch ----------------
__device__ __half g_h1[2][Bsz * Hh];     // y(tau) lives in buffer tau&1
__device__ __half g_h2[2][Bsz * Hh];     // z(tau) lives in buffer tau&1
__device__ float  g_xT[Tt * Bsz];
__device__ unsigned g_f1[128];   // per-CTA flag: y(t) published  (value t+1)
__device__ unsigned g_f2[128];   // per-CTA flag: z(t+1) published (value t+1)

// ---------------- smem layout (byte offsets) ----------------
#define OFF_WP0   0         // 32KB  w_hh0 packed (WG0)
#define OFF_WP1H  32768     // 32KB  w_hh1 packed (WG1)
#define OFF_WP1X  65536     // 32KB  w_ih1 packed (WG1)
#define OFF_H1A   98304     // 33792 h1 tile (WG0 private)
#define OFF_H2    132096    // 33792 h2/h1 morphing tile (WG1 private)
#define OFF_ABUFA 165888    // 17408 fp32 gates 64x68 (WG0)
#define OFF_ABUFB 183296    // 17408 (WG1)
#define OFF_BIAS0 200704
#define OFF_WIH0  200960
#define OFF_BIAS1 201216
#define SMEM_BYTES 201472

// ---------------- helpers ----------------
__device__ __forceinline__ float tanh_a(float x) {
    float r; asm("tanh.approx.f32 %0, %1;" : "=f"(r) : "f"(x)); return r;
}
__device__ __forceinline__ float sigm(float x) {
    return fmaf(tanh_a(0.5f * x), 0.5f, 0.5f);
}
__device__ __forceinline__ unsigned sptr(const void* p) {
    return (unsigned)__cvta_generic_to_shared(p);
}
__device__ __forceinline__ void cpasync16(unsigned saddr, const void* g) {
    asm volatile("cp.async.cg.shared.global [%0], [%1], 16;" :: "r"(saddr), "l"(g));
}
#define CP_COMMIT() asm volatile("cp.async.commit_group;")
#define CP_WAIT(n)  asm volatile("cp.async.wait_group %0;" :: "n"(n))
#define BAR_SYNC(id, n)   asm volatile("bar.sync %0, %1;"   :: "r"(id), "n"(n) : "memory")

__device__ __forceinline__ void mma16816(float d[4], const unsigned a[4],
                                         unsigned b0, unsigned b1) {
    asm volatile(
        "mma.sync.aligned.m16n8k16.row.col.f32.f16.f16.f32 "
        "{%0,%1,%2,%3}, {%4,%5,%6,%7}, {%8,%9}, {%0,%1,%2,%3};"
        : "+f"(d[0]), "+f"(d[1]), "+f"(d[2]), "+f"(d[3])
        : "r"(a[0]), "r"(a[1]), "r"(a[2]), "r"(a[3]), "r"(b0), "r"(b1));
}

// Pack 64-gate x 256-k fp32 weight slice into fp16 B-fragment order (proven R6-R12).
__device__ void pack_weights(unsigned* dst, const float* __restrict__ W, int hs) {
    for (int idx = threadIdx.x; idx < 8192; idx += 256) {
        int q = idx & 3, lane = (idx >> 2) & 31, npair = (idx >> 7) & 3, kk = idx >> 9;
        int ntile = npair * 2 + (q >> 1), reg = q & 1;
        int n  = ntile * 8 + (lane >> 2);
        int k0 = kk * 16 + (lane & 3) * 2 + reg * 8;
        int grow = (n >> 4) * 256 + hs * 16 + (n & 15);   // gate order i,f,g,o
        __half2 v = __floats2half2_rn(W[grow * 256 + k0], W[grow * 256 + k0 + 1]);
        dst[idx] = *reinterpret_cast<unsigned*>(&v);
    }
}

// Stage a full 64x256 fp16 tile (32KB) with 128 threads via cp.async.cg (L2-coherent).
__device__ __forceinline__ void stage_tile128(void* dst, const __half* __restrict__ src,
                                              int wg_tid) {
    unsigned base = sptr(dst);
    #pragma unroll
    for (int i = 0; i < 16; i++) {
        int seg = wg_tid + i * 128;            // 2048 x 16B
        int row = seg >> 5, s = seg & 31;
        cpasync16(base + (unsigned)((row * STRD + s * 8) * 2),
                  src + row * 256 + s * 8);
    }
}

// Stage a 128-col half (16KB) of a 64-row tile with 128 threads.
__device__ __forceinline__ void stage_half128(void* dst, const __half* __restrict__ src,
                                              int half, int wg_tid) {
    unsigned base = sptr(dst);
    #pragma unroll
    for (int i = 0; i < 8; i++) {
        int seg = wg_tid + i * 128;            // 1024 x 16B
        int row = seg >> 4, s = seg & 15;
        int col = half * 128 + s * 8;
        cpasync16(base + (unsigned)((row * STRD + col) * 2),
                  src + row * 256 + col);
    }
}

// nsteps K=16 MMA steps: acc[32x32 per warp] += A @ W^T  (4 warps, 2x2 grid; proven)
__device__ __forceinline__ void gemm_ksteps(float acc[2][4][4], const __half* tile,
                                            const uint4* __restrict__ wp,
                                            int kbase, int nsteps, int kwoff,
                                            int wm, int wn, int lane) {
    unsigned sbase = sptr(tile);
    #pragma unroll 4
    for (int k = 0; k < nsteps; k++) {
        int kk = kbase + k;                    // column position in tile
        int kw = kwoff + k;                    // kstep index in weight pack
        unsigned a[2][4];
        int colb = kk * 16 + (lane >> 4) * 8;
        #pragma unroll
        for (int mt = 0; mt < 2; mt++) {
            int row = wm + mt * 16 + (lane & 7) + ((lane >> 3) & 1) * 8;
            unsigned ad = sbase + (unsigned)((row * STRD + colb) * 2);
            asm volatile("ldmatrix.sync.aligned.m8n8.x4.shared.b16 {%0,%1,%2,%3}, [%4];"
                : "=r"(a[mt][0]), "=r"(a[mt][1]), "=r"(a[mt][2]), "=r"(a[mt][3])
                : "r"(ad));
        }
        uint4 b01 = wp[(kw * 4 + (wn >> 4)) * 32 + lane];
        uint4 b23 = wp[(kw * 4 + (wn >> 4) + 1) * 32 + lane];
        #pragma unroll
        for (int mt = 0; mt < 2; mt++) {
            mma16816(acc[mt][0], a[mt], b01.x, b01.y);
            mma16816(acc[mt][1], a[mt], b01.z, b01.w);
            mma16816(acc[mt][2], a[mt], b23.x, b23.y);
            mma16816(acc[mt][3], a[mt], b23.z, b23.w);
        }
    }
}

__device__ __forceinline__ void store_gates(float acc[2][4][4], float* abuf,
                                            int wm, int wn, int lane) {
    #pragma unroll
    for (int mt = 0; mt < 2; mt++)
        #pragma unroll
        for (int nt = 0; nt < 4; nt++) {
            int r  = wm + mt * 16 + (lane >> 2);
            int cc = wn + nt * 8 + (lane & 3) * 2;
            abuf[r * 68 + cc]           = acc[mt][nt][0];
            abuf[r * 68 + cc + 1]       = acc[mt][nt][1];
            abuf[(r + 8) * 68 + cc]     = acc[mt][nt][2];
            abuf[(r + 8) * 68 + cc + 1] = acc[mt][nt][3];
        }
}

#define ZERO_ACC(acc)                                              \
    _Pragma("unroll") for (int mt = 0; mt < 2; mt++)               \
    _Pragma("unroll") for (int nt = 0; nt < 4; nt++)               \
    _Pragma("unroll") for (int q = 0; q < 4; q++) acc[mt][nt][q] = 0.0f;

// Poll the group's 16 per-CTA flags until all >= target (proven R11 pattern).
// barid 1 = WG0, barid 2 = WG1. The bar doubles as an intra-WG execution barrier.
__device__ __forceinline__ void wait_flags(volatile unsigned* f, unsigned target,
                                           int wg_tid, int barid) {
    if (wg_tid < GSIZE) {
        while (f[wg_tid] < target) __nanosleep(32);
    }
    __threadfence();
    if (barid == 1) { BAR_SYNC(1, 128); } else { BAR_SYNC(2, 128); }
}

// ---------------- kernels ----------------
__global__ void reset_kernel(const float* __restrict__ x) {
    int idx = blockIdx.x * blockDim.x + threadIdx.x;   // 131072
    g_h1[0][idx] = __float2half(0.0f);
    g_h2[0][idx] = __float2half(0.0f);
    int t = idx >> 9, b = idx & 511;
    g_xT[idx] = x[b * Tt + t];
    if (idx < 128) { g_f1[idx] = 0u; g_f2[idx] = 0u; }
}

__global__ void __launch_bounds__(256, 1)
lstm_main(const float* __restrict__ w_ih0, const float* __restrict__ w_hh0,
          const float* __restrict__ b_ih0, const float* __restrict__ b_hh0,
          const float* __restrict__ w_ih1, const float* __restrict__ w_hh1,
          const float* __restrict__ b_ih1, const float* __restrict__ b_hh1)
{
    extern __shared__ char smem[];
    const uint4* wp0  = (const uint4*)(smem + OFF_WP0);
    const uint4* wp1h = (const uint4*)(smem + OFF_WP1H);
    const uint4* wp1x = (const uint4*)(smem + OFF_WP1X);
    const __half* tH1 = (const __half*)(smem + OFF_H1A);
    const __half* tH2 = (const __half*)(smem + OFF_H2);
    float* abufA = (float*)(smem + OFF_ABUFA);
    float* abufB = (float*)(smem + OFF_ABUFB);
    float* bias0 = (float*)(smem + OFF_BIAS0);
    float* wih0c = (float*)(smem + OFF_WIH0);
    float* bias1 = (float*)(smem + OFF_BIAS1);

    const int tid    = threadIdx.x;
    const int wg_tid = tid & 127;
    const int lane   = tid & 31;
    const int warp   = tid >> 5;
    const int bg     = blockIdx.x >> 4;
    const int hs     = blockIdx.x & 15;
    const int brow0  = bg * 64;
    const int cta    = blockIdx.x;

    pack_weights((unsigned*)(smem + OFF_WP0),  w_hh0, hs);
    pack_weights((unsigned*)(smem + OFF_WP1H), w_hh1, hs);
    pack_weights((unsigned*)(smem + OFF_WP1X), w_ih1, hs);
    if (tid < 64) {
        int n = tid, gt = n >> 4, hloc = n & 15;
        int grow = gt * 256 + hs * 16 + hloc;
        bias0[n] = b_ih0[grow] + b_hh0[grow];
        wih0c[n] = w_ih0[grow];
        bias1[n] = b_ih1[grow] + b_hh1[grow];
    }
    __syncthreads();

    volatile unsigned* f1g = g_f1 + bg * GSIZE;
    volatile unsigned* f2g = g_f2 + bg * GSIZE;
    const int b   = wg_tid >> 1;           // batch row in tile (0..63)
    const int hh0 = (wg_tid & 1) * 8;      // h-subrange within 16-slice

    if (warp < 4) {
        // ================= WG0: layer-0 pipeline (fully self-contained) ==========
        const int wm = (warp & 1) * 32, wn = ((warp >> 1) & 1) * 32;
        float c0[8];
        #pragma unroll
        for (int j = 0; j < 8; j++) c0[j] = 0.0f;

        // prologue: stage y(-1) = zeros (g_h1[0] zeroed by reset, buffer (0-? ) ok)
        stage_tile128(smem + OFF_H1A, (const __half*)g_h1[0] + brow0 * 256, wg_tid);
        CP_COMMIT(); CP_WAIT(0);
        BAR_SYNC(1, 128);

        #pragma unroll 1
        for (int t = 0; t < Tt; t++) {
            float xv = g_xT[t * Bsz + brow0 + b];

            float acc[2][4][4];
            ZERO_ACC(acc);
            gemm_ksteps(acc, tH1, wp0, 0, 16, 0, wm, wn, lane);
            store_gates(acc, abufA, wm, wn, lane);
            BAR_SYNC(1, 128);

            // WAR guard: all WG1s finished reading y(t-2) (published with f2 = t-1)
            wait_flags(f2g, (unsigned)(t >= 1 ? t - 1 : 0), wg_tid, 1);

            const float* ab = abufA + b * 68 + hh0;
            float G[4][8];
            #pragma unroll
            for (int gt = 0; gt < 4; gt++) {
                *(float4*)&G[gt][0] = *(const float4*)(ab + gt * 16);
                *(float4*)&G[gt][4] = *(const float4*)(ab + gt * 16 + 4);
            }
            __half hv[8];
            #pragma unroll
            for (int j = 0; j < 8; j++) {
                int h = hh0 + j;
                float gi = G[0][j] + xv * wih0c[h]      + bias0[h];
                float gf = G[1][j] + xv * wih0c[16 + h] + bias0[16 + h];
                float gg = G[2][j] + xv * wih0c[32 + h] + bias0[32 + h];
                float go = G[3][j] + xv * wih0c[48 + h] + bias0[48 + h];
                float iv = sigm(gi), fv = sigm(gf), gv = tanh_a(gg), ov = sigm(go);
                c0[j] = fv * c0[j] + iv * gv;
                hv[j] = __float2half(ov * tanh_a(c0[j]));
            }
            *(uint4*)(&g_h1[(t + 1) & 1][(brow0 + b) * 256 + hs * 16 + hh0])
                = *(uint4*)hv;

            __threadfence();
            BAR_SYNC(1, 128);
            if (wg_tid == 0) atomicExch(&g_f1[cta], (unsigned)(t + 1));

            // restage tH1 <- y(t) for next iteration's gemmA
            wait_flags(f1g, (unsigned)(t + 1), wg_tid, 1);
            stage_tile128(smem + OFF_H1A,
                          (const __half*)g_h1[(t + 1) & 1] + brow0 * 256, wg_tid);
            CP_COMMIT(); CP_WAIT(0);
            BAR_SYNC(1, 128);
        }
    } else {
        // ================= WG1: layer-1 pipeline (self-staged h1) =================
        const int w = warp - 4;
        const int wm = (w & 1) * 32, wn = ((w >> 1) & 1) * 32;
        float c1[8];
        #pragma unroll
        for (int j = 0; j < 8; j++) c1[j] = 0.0f;

        #pragma unroll 1
        for (int t = 0; t < Tt; t++) {
            const __half* ysrc = (const __half*)g_h1[(t + 1) & 1] + brow0 * 256;

            // stage z(t), gemm1 first half
            wait_flags(f2g, (unsigned)t, wg_tid, 2);
            stage_tile128(smem + OFF_H2, (const __half*)g_h2[t & 1] + brow0 * 256,
                          wg_tid);
            CP_COMMIT(); CP_WAIT(0);
            BAR_SYNC(2, 128);

            float acc[2][4][4];
            ZERO_ACC(acc);
            gemm_ksteps(acc, tH2, wp1h, 0, 8, 0, wm, wn, lane);

            // cols 0-127 of tH2 now dead: overwrite with y(t) while k8-15 run
            wait_flags(f1g, (unsigned)(t + 1), wg_tid, 2);   // bar also fences k0-7
            stage_half128(smem + OFF_H2, ysrc, 0, wg_tid);
            CP_COMMIT();
            gemm_ksteps(acc, tH2, wp1h, 8, 8, 8, wm, wn, lane);
            BAR_SYNC(2, 128);                                // all warps done k8-15
            stage_half128(smem + OFF_H2, ysrc, 1, wg_tid);
            CP_COMMIT();

            // gemm2 on the morphing buffer (now y(t))
            CP_WAIT(1);
            BAR_SYNC(2, 128);
            gemm_ksteps(acc, tH2, wp1x, 0, 8, 0, wm, wn, lane);
            CP_WAIT(0);
            BAR_SYNC(2, 128);
            gemm_ksteps(acc, tH2, wp1x, 8, 8, 8, wm, wn, lane);
            store_gates(acc, abufB, wm, wn, lane);
            BAR_SYNC(2, 128);

            const float* ab = abufB + b * 68 + hh0;
            float G[4][8];
            #pragma unroll
            for (int gt = 0; gt < 4; gt++) {
                *(float4*)&G[gt][0] = *(const float4*)(ab + gt * 16);
                *(float4*)&G[gt][4] = *(const float4*)(ab + gt * 16 + 4);
            }
            __half hv[8];
            #pragma unroll
            for (int j = 0; j < 8; j++) {
                int h = hh0 + j;
                float gi = G[0][j] + bias1[h];
                float gf = G[1][j] + bias1[16 + h];
                float gg = G[2][j] + bias1[32 + h];
                float go = G[3][j] + bias1[48 + h];
                float iv = sigm(gi), fv = sigm(gf), gv = tanh_a(gg), ov = sigm(go);
                c1[j] = fv * c1[j] + iv * gv;
                hv[j] = __float2half(ov * tanh_a(c1[j]));
            }
            *(uint4*)(&g_h2[(t + 1) & 1][(brow0 + b) * 256 + hs * 16 + hh0])
                = *(uint4*)hv;

            __threadfence();
            BAR_SYNC(2, 128);
            if (wg_tid == 0) atomicExch(&g_f2[cta], (unsigned)(t + 1));
        }
    }
}

__global__ void epilogue_kernel(const float* __restrict__ w_lin,
                                const float* __restrict__ b_lin,
                                float* __restrict__ out) {
    int b = blockIdx.x;
    int lane = threadIdx.x;            // 32 threads
    float hv[8];
    #pragma unroll
    for (int j = 0; j < 8; j++)
        hv[j] = __half2float(g_h2[0][b * Hh + lane + j * 32]);   // z(256) in buffer 0
    for (int p = 0; p < Pp; p++) {
        float s = 0.0f;
        #pragma unroll
        for (int j = 0; j < 8; j++)
            s += hv[j] * w_lin[p * Hh + lane + j * 32];
        #pragma unroll
        for (int off = 16; off > 0; off >>= 1)
            s += __shfl_xor_sync(0xFFFFFFFFu, s, off);
        if (lane == 0) out[b * Pp + p] = s + b_lin[p];
    }
}

// ---------------- launch ----------------
extern "C" void kernel_launch(void* const* d_in, const int* in_sizes, int n_in,
                              void* d_out, int out_size) {
    const float* x     = (const float*)d_in[0];
    const float* w_ih0 = (const float*)d_in[1];
    const float* w_hh0 = (const float*)d_in[2];
    const float* b_ih0 = (const float*)d_in[3];
    const float* b_hh0 = (const float*)d_in[4];
    const float* w_ih1 = (const float*)d_in[5];
    const float* w_hh1 = (const float*)d_in[6];
    const float* b_ih1 = (const float*)d_in[7];
    const float* b_hh1 = (const float*)d_in[8];
    const float* w_lin = (const float*)d_in[9];
    const float* b_lin = (const float*)d_in[10];

    cudaFuncSetAttribute(lstm_main, cudaFuncAttributeMaxDynamicSharedMemorySize,
                         SMEM_BYTES);

    reset_kernel<<<512, 256>>>(x);
    lstm_main<<<128, 256, SMEM_BYTES>>>(w_ih0, w_hh0, b_ih0, b_hh0,
                                        w_ih1, w_hh1, b_ih1, b_hh1);
    epilogue_kernel<<<Bsz, 32>>>(w_lin, b_lin, (float*)d_out);
}

// round 16
// speedup vs baseline: 1.3931x; 1.3931x over previous
#include <cuda_runtime.h>
#include <cuda_fp16.h>
#include <cstdint>

#define Bsz 512
#define Tt  256
#define Hh  256
#define Pp  14
#define GSIZE 16
#define STRD 264   // staging row stride in halves (528B: ldmatrix conflict-free)

// ---------------- global scratch ----------------
__device__ __half g_h1[2][Bsz * Hh];
__device__ __half g_h2[2][Bsz * Hh];
__device__ float  g_xT[Tt * Bsz];
__device__ unsigned g_f1[128];   // per-CTA step flag: h1(t+1) published
__device__ unsigned g_f2[128];   // per-CTA step flag: h2(t+1) published

// ---------------- smem layout (byte offsets) ----------------
#define OFF_WP0   0         // 32KB  w_hh0 packed (WG0)
#define OFF_WP1H  32768     // 32KB  w_hh1 packed (WG1)
#define OFF_WP1X  65536     // 32KB  w_ih1 packed (WG1)
#define OFF_H1A   98304     // 33792 h1 tile 64x256 @ stride 264 (WG0 stages, both read)
#define OFF_H2    132096    // 33792 h2 tile (WG1)
#define OFF_ABUFA 165888    // 17408 fp32 gates 64x68 (WG0)
#define OFF_ABUFB 183296    // 17408 (WG1)
#define OFF_BIAS0 200704
#define OFF_WIH0  200960
#define OFF_BIAS1 201216
#define SMEM_BYTES 201472

// ---------------- helpers ----------------
__device__ __forceinline__ float tanh_a(float x) {
    float r; asm("tanh.approx.f32 %0, %1;" : "=f"(r) : "f"(x)); return r;
}
__device__ __forceinline__ float sigm(float x) {
    return fmaf(tanh_a(0.5f * x), 0.5f, 0.5f);
}
__device__ __forceinline__ unsigned sptr(const void* p) {
    return (unsigned)__cvta_generic_to_shared(p);
}
__device__ __forceinline__ void cpasync16(unsigned saddr, const void* g) {
    asm volatile("cp.async.cg.shared.global [%0], [%1], 16;" :: "r"(saddr), "l"(g));
}
#define CP_COMMIT() asm volatile("cp.async.commit_group;")
#define CP_WAIT(n)  asm volatile("cp.async.wait_group %0;" :: "n"(n))
#define BAR_SYNC(id, n)   asm volatile("bar.sync %0, %1;"   :: "r"(id), "n"(n) : "memory")
#define BAR_ARRIVE(id, n) asm volatile("bar.arrive %0, %1;" :: "r"(id), "n"(n) : "memory")

__device__ __forceinline__ void mma16816(float d[4], const unsigned a[4],
                                         unsigned b0, unsigned b1) {
    asm volatile(
        "mma.sync.aligned.m16n8k16.row.col.f32.f16.f16.f32 "
        "{%0,%1,%2,%3}, {%4,%5,%6,%7}, {%8,%9}, {%0,%1,%2,%3};"
        : "+f"(d[0]), "+f"(d[1]), "+f"(d[2]), "+f"(d[3])
        : "r"(a[0]), "r"(a[1]), "r"(a[2]), "r"(a[3]), "r"(b0), "r"(b1));
}

// Pack 64-gate x 256-k fp32 weight slice into fp16 B-fragment order (proven R6-R11).
__device__ void pack_weights(unsigned* dst, const float* __restrict__ W, int hs) {
    for (int idx = threadIdx.x; idx < 8192; idx += 256) {
        int q = idx & 3, lane = (idx >> 2) & 31, npair = (idx >> 7) & 3, kk = idx >> 9;
        int ntile = npair * 2 + (q >> 1), reg = q & 1;
        int n  = ntile * 8 + (lane >> 2);
        int k0 = kk * 16 + (lane & 3) * 2 + reg * 8;
        int grow = (n >> 4) * 256 + hs * 16 + (n & 15);   // gate order i,f,g,o
        __half2 v = __floats2half2_rn(W[grow * 256 + k0], W[grow * 256 + k0 + 1]);
        dst[idx] = *reinterpret_cast<unsigned*>(&v);
    }
}

// Stage a full 64x256 fp16 tile (32KB) with 128 threads via cp.async.cg (L2-coherent).
__device__ __forceinline__ void stage_tile128(void* dst, const __half* __restrict__ src,
                                              int wg_tid) {
    unsigned base = sptr(dst);
    #pragma unroll
    for (int i = 0; i < 16; i++) {
        int seg = wg_tid + i * 128;            // 2048 x 16B
        int row = seg >> 5, s = seg & 31;
        cpasync16(base + (unsigned)((row * STRD + s * 8) * 2),
                  src + row * 256 + s * 8);
    }
}

// Stage a 128-col half (16KB) of a 64-row tile with 128 threads.
__device__ __forceinline__ void stage_half128(void* dst, const __half* __restrict__ src,
                                              int half, int wg_tid) {
    unsigned base = sptr(dst);
    #pragma unroll
    for (int i = 0; i < 8; i++) {
        int seg = wg_tid + i * 128;            // 1024 x 16B
        int row = seg >> 4, s = seg & 15;
        int col = half * 128 + s * 8;
        cpasync16(base + (unsigned)((row * STRD + col) * 2),
                  src + row * 256 + col);
    }
}

// nsteps K=16 MMA steps: acc[32x32 per warp] += A @ W^T  (4 warps, 2x2 grid; proven R11)
__device__ __forceinline__ void gemm_ksteps(float acc[2][4][4], const __half* tile,
                                            const uint4* __restrict__ wp,
                                            int kbase, int nsteps,
                                            int wm, int wn, int lane) {
    unsigned sbase = sptr(tile);
    #pragma unroll 4
    for (int k = 0; k < nsteps; k++) {
        int kk = kbase + k;
        unsigned a[2][4];
        int colb = kk * 16 + (lane >> 4) * 8;
        #pragma unroll
        for (int mt = 0; mt < 2; mt++) {
            int row = wm + mt * 16 + (lane & 7) + ((lane >> 3) & 1) * 8;
            unsigned ad = sbase + (unsigned)((row * STRD + colb) * 2);
            asm volatile("ldmatrix.sync.aligned.m8n8.x4.shared.b16 {%0,%1,%2,%3}, [%4];"
                : "=r"(a[mt][0]), "=r"(a[mt][1]), "=r"(a[mt][2]), "=r"(a[mt][3])
                : "r"(ad));
        }
        uint4 b01 = wp[(kk * 4 + (wn >> 4)) * 32 + lane];
        uint4 b23 = wp[(kk * 4 + (wn >> 4) + 1) * 32 + lane];
        #pragma unroll
        for (int mt = 0; mt < 2; mt++) {
            mma16816(acc[mt][0], a[mt], b01.x, b01.y);
            mma16816(acc[mt][1], a[mt], b01.z, b01.w);
            mma16816(acc[mt][2], a[mt], b23.x, b23.y);
            mma16816(acc[mt][3], a[mt], b23.z, b23.w);
        }
    }
}

__device__ __forceinline__ void store_gates(float acc[2][4][4], float* abuf,
                                            int wm, int wn, int lane) {
    #pragma unroll
    for (int mt = 0; mt < 2; mt++)
        #pragma unroll
        for (int nt = 0; nt < 4; nt++) {
            int r  = wm + mt * 16 + (lane >> 2);
            int cc = wn + nt * 8 + (lane & 3) * 2;
            abuf[r * 68 + cc]           = acc[mt][nt][0];
            abuf[r * 68 + cc + 1]       = acc[mt][nt][1];
            abuf[(r + 8) * 68 + cc]     = acc[mt][nt][2];
            abuf[(r + 8) * 68 + cc + 1] = acc[mt][nt][3];
        }
}

#define ZERO_ACC(acc)                                              \
    _Pragma("unroll") for (int mt = 0; mt < 2; mt++)               \
    _Pragma("unroll") for (int nt = 0; nt < 4; nt++)               \
    _Pragma("unroll") for (int q = 0; q < 4; q++) acc[mt][nt][q] = 0.0f;

// Poll the group's 16 per-CTA flags until all >= target (R11-proven pattern).
__device__ __forceinline__ void wait_flags(volatile unsigned* f, unsigned target,
                                           int wg_tid, int barid) {
    if (wg_tid < GSIZE) {
        while (f[wg_tid] < target) __nanosleep(32);
    }
    __threadfence();
    if (barid == 1) { BAR_SYNC(1, 128); } else { BAR_SYNC(2, 128); }
}

// ---------------- kernels ----------------
__global__ void reset_kernel(const float* __restrict__ x) {
    int idx = blockIdx.x * blockDim.x + threadIdx.x;   // 131072
    g_h1[0][idx] = __float2half(0.0f);
    g_h2[0][idx] = __float2half(0.0f);
    int t = idx >> 9, b = idx & 511;
    g_xT[idx] = x[b * Tt + t];
    if (idx < 128) { g_f1[idx] = 0u; g_f2[idx] = 0u; }
}

__global__ void __launch_bounds__(256, 1)
lstm_main(const float* __restrict__ w_ih0, const float* __restrict__ w_hh0,
          const float* __restrict__ b_ih0, const float* __restrict__ b_hh0,
          const float* __restrict__ w_ih1, const float* __restrict__ w_hh1,
          const float* __restrict__ b_ih1, const float* __restrict__ b_hh1)
{
    extern __shared__ char smem[];
    const uint4* wp0  = (const uint4*)(smem + OFF_WP0);
    const uint4* wp1h = (const uint4*)(smem + OFF_WP1H);
    const uint4* wp1x = (const uint4*)(smem + OFF_WP1X);
    const __half* tH1 = (const __half*)(smem + OFF_H1A);
    const __half* tH2 = (const __half*)(smem + OFF_H2);
    float* abufA = (float*)(smem + OFF_ABUFA);
    float* abufB = (float*)(smem + OFF_ABUFB);
    float* bias0 = (float*)(smem + OFF_BIAS0);
    float* wih0c = (float*)(smem + OFF_WIH0);
    float* bias1 = (float*)(smem + OFF_BIAS1);

    const int tid    = threadIdx.x;
    const int wg_tid = tid & 127;
    const int lane   = tid & 31;
    const int warp   = tid >> 5;
    const int bg     = blockIdx.x >> 4;
    const int hs     = blockIdx.x & 15;
    const int brow0  = bg * 64;
    const int cta    = blockIdx.x;

    pack_weights((unsigned*)(smem + OFF_WP0),  w_hh0, hs);
    pack_weights((unsigned*)(smem + OFF_WP1H), w_hh1, hs);
    pack_weights((unsigned*)(smem + OFF_WP1X), w_ih1, hs);
    if (tid < 64) {
        int n = tid, gt = n >> 4, hloc = n & 15;
        int grow = gt * 256 + hs * 16 + hloc;
        bias0[n] = b_ih0[grow] + b_hh0[grow];
        wih0c[n] = w_ih0[grow];
        bias1[n] = b_ih1[grow] + b_hh1[grow];
    }
    __syncthreads();

    volatile unsigned* f1g = g_f1 + bg * GSIZE;
    volatile unsigned* f2g = g_f2 + bg * GSIZE;
    const int b   = wg_tid >> 1;           // batch row in tile (0..63)
    const int hh0 = (wg_tid & 1) * 8;      // h-subrange within 16-slice

    if (warp < 4) {
        // ================= WG0: layer-0 pipeline =================
        const int wm = (warp & 1) * 32, wn = ((warp >> 1) & 1) * 32;
        float c0[8];
        #pragma unroll
        for (int j = 0; j < 8; j++) c0[j] = 0.0f;

        // prologue: stage h1(0) (zeros)
        stage_tile128(smem + OFF_H1A, (const __half*)g_h1[0] + brow0 * 256, wg_tid);
        CP_COMMIT(); CP_WAIT(0);
        BAR_SYNC(1, 128);

        #pragma unroll 1
        for (int t = 0; t < Tt; t++) {
            float xv = g_xT[t * Bsz + brow0 + b];

            float acc[2][4][4];
            ZERO_ACC(acc);
            gemm_ksteps(acc, tH1, wp0, 0, 16, wm, wn, lane);
            store_gates(acc, abufA, wm, wn, lane);
            BAR_SYNC(1, 128);

            // pointwise (vectorized gate loads)
            const float* ab = abufA + b * 68 + hh0;
            float G[4][8];
            #pragma unroll
            for (int gt = 0; gt < 4; gt++) {
                *(float4*)&G[gt][0] = *(const float4*)(ab + gt * 16);
                *(float4*)&G[gt][4] = *(const float4*)(ab + gt * 16 + 4);
            }
            __half hv[8];
            #pragma unroll
            for (int j = 0; j < 8; j++) {
                int h = hh0 + j;
                float gi = G[0][j] + xv * wih0c[h]      + bias0[h];
                float gf = G[1][j] + xv * wih0c[16 + h] + bias0[16 + h];
                float gg = G[2][j] + xv * wih0c[32 + h] + bias0[32 + h];
                float go = G[3][j] + xv * wih0c[48 + h] + bias0[48 + h];
                float iv = sigm(gi), fv = sigm(gf), gv = tanh_a(gg), ov = sigm(go);
                c0[j] = fv * c0[j] + iv * gv;
                hv[j] = __float2half(ov * tanh_a(c0[j]));
            }
            *(uint4*)(&g_h1[(t + 1) & 1][(brow0 + b) * 256 + hs * 16 + hh0])
                = *(uint4*)hv;

            __threadfence();
            BAR_SYNC(1, 128);
            if (wg_tid == 0) atomicExch(&g_f1[cta], (unsigned)(t + 1));

            wait_flags(f1g, (unsigned)(t + 1), wg_tid, 1);   // all group h1(t+1) ready
            BAR_SYNC(3, 256);     // WG1 finished reading h1(t) from stgH1A
            stage_tile128(smem + OFF_H1A,
                          (const __half*)g_h1[(t + 1) & 1] + brow0 * 256, wg_tid);
            CP_COMMIT(); CP_WAIT(0);
            BAR_SYNC(1, 128);
            BAR_ARRIVE(4, 256);   // publish: stgH1A = h1(t+1)
        }
    } else {
        // ================= WG1: layer-1 pipeline =================
        const int w = warp - 4;
        const int wm = (w & 1) * 32, wn = ((w >> 1) & 1) * 32;
        float c1[8];
        #pragma unroll
        for (int j = 0; j < 8; j++) c1[j] = 0.0f;

        BAR_ARRIVE(3, 256);       // priming: allow WG0's first restage

        #pragma unroll 1
        for (int t = 0; t < Tt; t++) {
            const __half* h2src = (const __half*)g_h2[t & 1] + brow0 * 256;

            wait_flags(f2g, (unsigned)t, wg_tid, 2);          // all group h2(t) ready
            // split stage: overlap second half with gemm1's first 8 ksteps
            stage_half128(smem + OFF_H2, h2src, 0, wg_tid); CP_COMMIT();
            stage_half128(smem + OFF_H2, h2src, 1, wg_tid); CP_COMMIT();

            float acc[2][4][4];
            ZERO_ACC(acc);
            CP_WAIT(1);
            BAR_SYNC(2, 128);
            gemm_ksteps(acc, tH2, wp1h, 0, 8, wm, wn, lane);
            CP_WAIT(0);
            BAR_SYNC(2, 128);
            gemm_ksteps(acc, tH2, wp1h, 8, 8, wm, wn, lane);

            BAR_SYNC(4, 256);     // stgH1A = h1(t+1) ready (from WG0)
            gemm_ksteps(acc, tH1, wp1x, 0, 16, wm, wn, lane);
            store_gates(acc, abufB, wm, wn, lane);
            BAR_SYNC(2, 128);
            BAR_ARRIVE(3, 256);   // done reading stgH1A; WG0 may restage

            // pointwise (vectorized gate loads)
            const float* ab = abufB + b * 68 + hh0;
            float G[4][8];
            #pragma unroll
            for (int gt = 0; gt < 4; gt++) {
                *(float4*)&G[gt][0] = *(const float4*)(ab + gt * 16);
                *(float4*)&G[gt][4] = *(const float4*)(ab + gt * 16 + 4);
            }
            __half hv[8];
            #pragma unroll
            for (int j = 0; j < 8; j++) {
                int h = hh0 + j;
                float gi = G[0][j] + bias1[h];
                float gf = G[1][j] + bias1[16 + h];
                float gg = G[2][j] + bias1[32 + h];
                float go = G[3][j] + bias1[48 + h];
                float iv = sigm(gi), fv = sigm(gf), gv = tanh_a(gg), ov = sigm(go);
                c1[j] = fv * c1[j] + iv * gv;
                hv[j] = __float2half(ov * tanh_a(c1[j]));
            }
            *(uint4*)(&g_h2[(t + 1) & 1][(brow0 + b) * 256 + hs * 16 + hh0])
                = *(uint4*)hv;

            __threadfence();
            BAR_SYNC(2, 128);
            if (wg_tid == 0) atomicExch(&g_f2[cta], (unsigned)(t + 1));
        }
    }
}

__global__ void epilogue_kernel(const float* __restrict__ w_lin,
                                const float* __restrict__ b_lin,
                                float* __restrict__ out) {
    int b = blockIdx.x;
    int lane = threadIdx.x;            // 32 threads
    float hv[8];
    #pragma unroll
    for (int j = 0; j < 8; j++)
        hv[j] = __half2float(g_h2[0][b * Hh + lane + j * 32]);   // (255+1)&1 = 0
    for (int p = 0; p < Pp; p++) {
        float s = 0.0f;
        #pragma unroll
        for (int j = 0; j < 8; j++)
            s += hv[j] * w_lin[p * Hh + lane + j * 32];
        #pragma unroll
        for (int off = 16; off > 0; off >>= 1)
            s += __shfl_xor_sync(0xFFFFFFFFu, s, off);
        if (lane == 0) out[b * Pp + p] = s + b_lin[p];
    }
}

// ---------------- launch ----------------
extern "C" void kernel_launch(void* const* d_in, const int* in_sizes, int n_in,
                              void* d_out, int out_size) {
    const float* x     = (const float*)d_in[0];
    const float* w_ih0 = (const float*)d_in[1];
    const float* w_hh0 = (const float*)d_in[2];
    const float* b_ih0 = (const float*)d_in[3];
    const float* b_hh0 = (const float*)d_in[4];
    const float* w_ih1 = (const float*)d_in[5];
    const float* w_hh1 = (const float*)d_in[6];
    const float* b_ih1 = (const float*)d_in[7];
    const float* b_hh1 = (const float*)d_in[8];
    const float* w_lin = (const float*)d_in[9];
    const float* b_lin = (const float*)d_in[10];

    cudaFuncSetAttribute(lstm_main, cudaFuncAttributeMaxDynamicSharedMemorySize,
                         SMEM_BYTES);

    reset_kernel<<<512, 256>>>(x);
    lstm_main<<<128, 256, SMEM_BYTES>>>(w_ih0, w_hh0, b_ih0, b_hh0,
                                        w_ih1, w_hh1, b_ih1, b_hh1);
    epilogue_kernel<<<Bsz, 32>>>(w_lin, b_lin, (float*)d_out);
}